// round 2
// baseline (speedup 1.0000x reference)
#include <cuda_runtime.h>

#define BATCH 8
#define DIM   128
#define NTOK  32768          // 128*256
#define SPLIT 32
#define CHUNK (NTOK/SPLIT)   // 1024 tokens per k1 block
#define TN    32             // n-tile
#define PAD   132            // smem row pitch (floats), 528B = 16B-aligned

typedef unsigned long long u64;
typedef unsigned int u32;

// ---------------- scratch (no allocations allowed) ----------------
__device__ __align__(16) float g_KVp[BATCH][SPLIT][DIM * DIM];   // 16.8 MB partials
__device__ __align__(16) float g_KV[BATCH][DIM * DIM];
__device__ __align__(16) float g_Ksump[BATCH][SPLIT][DIM];
__device__ __align__(16) float g_Ksum[BATCH][DIM];

// ---------------- packed f32x2 helpers (sm_103a) ----------------
__device__ __forceinline__ u64 pack2(float x, float y) {
    u64 r;
    u32 xi = __float_as_uint(x), yi = __float_as_uint(y);
    asm("mov.b64 %0, {%1, %2};" : "=l"(r) : "r"(xi), "r"(yi));
    return r;
}
__device__ __forceinline__ void fma2(u64& d, u64 a, u64 b) {
    asm("fma.rn.f32x2 %0, %1, %2, %0;" : "+l"(d) : "l"(a), "l"(b));
}
__device__ __forceinline__ u64 mul2(u64 a, u64 b) {
    u64 r;
    asm("mul.rn.f32x2 %0, %1, %2;" : "=l"(r) : "l"(a), "l"(b));
    return r;
}

// phi(x) = elu(x) + 1 = x+1 (x>0) else exp(x)
__device__ __forceinline__ float phi(float x) {
    return x > 0.0f ? x + 1.0f : __expf(x);
}

// ====================================================================
// k1: partial KV[d][e] = sum_n phi(K[d,n]) * V[e,n]  and partial Ksum[d]
// grid (SPLIT, BATCH), 256 threads. 8x8 register tile per thread.
// ====================================================================
__global__ __launch_bounds__(256, 2)
void k1_kv(const float* __restrict__ k, const float* __restrict__ v) {
    const int b = blockIdx.y, s = blockIdx.x;
    const int tid = threadIdx.x;
    const int tx = tid & 15;      // e-tile index (8 cols = 4 pairs)
    const int ty = tid >> 4;      // d-tile index (8 rows)
    const int nf4 = tid & 7;      // loader: float4 index along n
    const int drow = tid >> 3;    // loader: row within 32-row pass

    __shared__ float sk[TN][PAD]; // phi(K), [n][d]
    __shared__ float sv[TN][PAD]; // V,      [n][e]

    u64 acc[8][4];
#pragma unroll
    for (int i = 0; i < 8; i++)
#pragma unroll
        for (int j = 0; j < 4; j++) acc[i][j] = 0ull;

    float ksum_acc[4] = {0.f, 0.f, 0.f, 0.f};

    const float* kb = k + (size_t)b * DIM * NTOK + (size_t)s * CHUNK;
    const float* vb = v + (size_t)b * DIM * NTOK + (size_t)s * CHUNK;

    for (int t0 = 0; t0 < CHUNK; t0 += TN) {
        __syncthreads();
        // load K,V tiles (transpose to [n][d]) — 4 passes of 32 rows
#pragma unroll
        for (int p = 0; p < 4; p++) {
            const int d = p * 32 + drow;
            float4 k4 = *reinterpret_cast<const float4*>(kb + (size_t)d * NTOK + t0 + nf4 * 4);
            float p0 = phi(k4.x), p1 = phi(k4.y), p2 = phi(k4.z), p3 = phi(k4.w);
            ksum_acc[p] += (p0 + p1) + (p2 + p3);
            sk[nf4 * 4 + 0][d] = p0;
            sk[nf4 * 4 + 1][d] = p1;
            sk[nf4 * 4 + 2][d] = p2;
            sk[nf4 * 4 + 3][d] = p3;
            float4 v4 = *reinterpret_cast<const float4*>(vb + (size_t)d * NTOK + t0 + nf4 * 4);
            sv[nf4 * 4 + 0][d] = v4.x;
            sv[nf4 * 4 + 1][d] = v4.y;
            sv[nf4 * 4 + 2][d] = v4.z;
            sv[nf4 * 4 + 3][d] = v4.w;
        }
        __syncthreads();

        for (int j = 0; j < TN; j++) {
            float4 a0 = *reinterpret_cast<const float4*>(&sk[j][ty * 8]);
            float4 a1 = *reinterpret_cast<const float4*>(&sk[j][ty * 8 + 4]);
            ulonglong2 v01 = *reinterpret_cast<const ulonglong2*>(&sv[j][tx * 8]);
            ulonglong2 v23 = *reinterpret_cast<const ulonglong2*>(&sv[j][tx * 8 + 4]);
            u64 ve[4] = {v01.x, v01.y, v23.x, v23.y};
            float kf[8] = {a0.x, a0.y, a0.z, a0.w, a1.x, a1.y, a1.z, a1.w};
#pragma unroll
            for (int i = 0; i < 8; i++) {
                u64 kd = pack2(kf[i], kf[i]);
#pragma unroll
                for (int jj = 0; jj < 4; jj++) fma2(acc[i][jj], kd, ve[jj]);
            }
        }
    }

    // write partial KV (STG.64 of packed pairs)
    float* outp = &g_KVp[b][s][0];
#pragma unroll
    for (int i = 0; i < 8; i++) {
        const int d = ty * 8 + i;
        u64* row = reinterpret_cast<u64*>(outp + d * DIM + tx * 8);
#pragma unroll
        for (int jj = 0; jj < 4; jj++) row[jj] = acc[i][jj];
    }

    // Ksum: 8 consecutive lanes (nf4 0..7) share each d -> shuffle reduce
#pragma unroll
    for (int p = 0; p < 4; p++) {
        float sv_ = ksum_acc[p];
        sv_ += __shfl_down_sync(0xffffffffu, sv_, 4, 8);
        sv_ += __shfl_down_sync(0xffffffffu, sv_, 2, 8);
        sv_ += __shfl_down_sync(0xffffffffu, sv_, 1, 8);
        if (nf4 == 0) g_Ksump[b][s][p * 32 + drow] = sv_;
    }
}

// ====================================================================
// k2: reduce split partials (deterministic, no atomics)
// ====================================================================
__global__ __launch_bounds__(256)
void k2_reduce() {
    const int idx = blockIdx.x * 256 + threadIdx.x; // 0 .. BATCH*DIM*DIM-1
    if (idx < BATCH * DIM * DIM) {
        const int b = idx >> 14;
        const int r = idx & (DIM * DIM - 1);
        float s = 0.f;
#pragma unroll
        for (int p = 0; p < SPLIT; p++) s += g_KVp[b][p][r];
        g_KV[b][r] = s;
    }
    if (idx < BATCH * DIM) {
        const int b = idx >> 7;
        const int d = idx & 127;
        float s = 0.f;
#pragma unroll
        for (int p = 0; p < SPLIT; p++) s += g_Ksump[b][p][d];
        g_Ksum[b][d] = s;
    }
}

// ====================================================================
// k3: out[e][t] = Z[t] * sum_d phi(Q[d,t]) * KV[d][e]
// grid (NTOK/128, BATCH), 256 threads, dyn smem ~131 KB
// ====================================================================
__global__ __launch_bounds__(256, 1)
void k3_out(const float* __restrict__ q, float* __restrict__ out) {
    const int b = blockIdx.y;
    const int t0 = blockIdx.x * 128;
    extern __shared__ float sm[];
    float* kv_s = sm;                       // [128][128]
    float* qp   = sm + DIM * DIM;           // [128][PAD]  phi(Q)
    float* ks   = qp + DIM * PAD;           // [128]
    float* zs   = ks + DIM;                 // [128]

    const int tid = threadIdx.x;
    const int tx = tid & 15;  // t-tile (8 cols = 4 pairs)
    const int ty = tid >> 4;  // e-tile (8 rows)

    // load KV (hot in L2)
    {
        const float4* src = reinterpret_cast<const float4*>(&g_KV[b][0]);
        float4* dst = reinterpret_cast<float4*>(kv_s);
        for (int i = tid; i < DIM * DIM / 4; i += 256) dst[i] = src[i];
    }
    // load Q tile, apply phi
    {
        const float* qb = q + (size_t)b * DIM * NTOK + t0;
        for (int i = tid; i < DIM * 32; i += 256) {
            const int d = i >> 5, c = i & 31;
            float4 x = *reinterpret_cast<const float4*>(qb + (size_t)d * NTOK + c * 4);
            float* row = qp + d * PAD + c * 4;
            row[0] = phi(x.x);
            row[1] = phi(x.y);
            row[2] = phi(x.z);
            row[3] = phi(x.w);
        }
    }
    if (tid < DIM) ks[tid] = g_Ksum[b][tid];
    __syncthreads();

    // Z per token
    if (tid < 128) {
        float s0 = 0.f, s1 = 0.f, s2 = 0.f, s3 = 0.f;
#pragma unroll 8
        for (int d = 0; d < 128; d += 4) {
            s0 += qp[(d + 0) * PAD + tid] * ks[d + 0];
            s1 += qp[(d + 1) * PAD + tid] * ks[d + 1];
            s2 += qp[(d + 2) * PAD + tid] * ks[d + 2];
            s3 += qp[(d + 3) * PAD + tid] * ks[d + 3];
        }
        zs[tid] = 1.0f / (((s0 + s1) + (s2 + s3)) + 1e-8f);
    }
    __syncthreads();

    u64 acc[8][4];
#pragma unroll
    for (int i = 0; i < 8; i++)
#pragma unroll
        for (int j = 0; j < 4; j++) acc[i][j] = 0ull;

    for (int d = 0; d < 128; d++) {
        float4 k0 = *reinterpret_cast<const float4*>(&kv_s[d * DIM + ty * 8]);
        float4 k1 = *reinterpret_cast<const float4*>(&kv_s[d * DIM + ty * 8 + 4]);
        ulonglong2 q01 = *reinterpret_cast<const ulonglong2*>(&qp[d * PAD + tx * 8]);
        ulonglong2 q23 = *reinterpret_cast<const ulonglong2*>(&qp[d * PAD + tx * 8 + 4]);
        u64 qv[4] = {q01.x, q01.y, q23.x, q23.y};
        float kf[8] = {k0.x, k0.y, k0.z, k0.w, k1.x, k1.y, k1.z, k1.w};
#pragma unroll
        for (int i = 0; i < 8; i++) {
            u64 kd = pack2(kf[i], kf[i]);
#pragma unroll
            for (int jj = 0; jj < 4; jj++) fma2(acc[i][jj], kd, qv[jj]);
        }
    }

    // epilogue: scale by z (packed along t), STG.64
    ulonglong2 z01 = *reinterpret_cast<const ulonglong2*>(&zs[tx * 8]);
    ulonglong2 z23 = *reinterpret_cast<const ulonglong2*>(&zs[tx * 8 + 4]);
    u64 zp[4] = {z01.x, z01.y, z23.x, z23.y};
#pragma unroll
    for (int i = 0; i < 8; i++) {
        const int e = ty * 8 + i;
        u64* orow = reinterpret_cast<u64*>(out + ((size_t)b * DIM + e) * NTOK + t0 + tx * 8);
#pragma unroll
        for (int jj = 0; jj < 4; jj++) orow[jj] = mul2(acc[i][jj], zp[jj]);
    }
}

// ====================================================================
extern "C" void kernel_launch(void* const* d_in, const int* in_sizes, int n_in,
                              void* d_out, int out_size) {
    const float* q = (const float*)d_in[0];
    const float* k = (const float*)d_in[1];
    const float* v = (const float*)d_in[2];
    float* out = (float*)d_out;

    const int smem3 = (DIM * DIM + DIM * PAD + DIM + DIM) * (int)sizeof(float); // 134144 B
    cudaFuncSetAttribute(k3_out, cudaFuncAttributeMaxDynamicSharedMemorySize, smem3);

    k1_kv<<<dim3(SPLIT, BATCH), 256>>>(k, v);
    k2_reduce<<<(BATCH * DIM * DIM) / 256, 256>>>();
    k3_out<<<dim3(NTOK / 128, BATCH), 256, smem3>>>(q, out);
}

// round 4
// speedup vs baseline: 1.9343x; 1.9343x over previous
#include <cuda_runtime.h>
#include <cuda_bf16.h>
#include <cstdint>

#define BATCH 8
#define DIM   128
#define NTOK  32768
#define SPLIT 32
#define CHUNK (NTOK/SPLIT)     // 1024 tokens per k1/k3 CTA
#define ITERS1 (CHUNK/64)      // 16 k1 iterations (64 tokens each)
#define TILES3 (CHUNK/64)      // 16 k3 tiles (64 tokens each)
#define EPS 1e-8f

typedef uint32_t u32;
typedef uint64_t u64;

// ---------------- scratch ----------------
__device__ __align__(16) float g_KVp[BATCH][SPLIT][DIM * DIM];   // fp32 KV partials
__device__ __align__(16) float g_Ksump[BATCH][SPLIT][DIM];
__device__ __align__(16) __nv_bfloat16 g_KVThi[BATCH][DIM * DIM]; // KV^T (row e, col d)
__device__ __align__(16) __nv_bfloat16 g_KVTlo[BATCH][DIM * DIM];
__device__ __align__(16) float g_Ksum[BATCH][DIM];

// ---------------- helpers ----------------
__device__ __forceinline__ u32 smem_u32(const void* p) {
    u32 a;
    asm("{ .reg .u64 t; cvta.to.shared.u64 t, %1; cvt.u32.u64 %0, t; }" : "=r"(a) : "l"(p));
    return a;
}
__device__ __forceinline__ void ldsm4(u32& r0, u32& r1, u32& r2, u32& r3, u32 addr) {
    asm volatile("ldmatrix.sync.aligned.m8n8.x4.shared.b16 {%0,%1,%2,%3}, [%4];"
                 : "=r"(r0), "=r"(r1), "=r"(r2), "=r"(r3) : "r"(addr));
}
__device__ __forceinline__ void mma16816(float* c, u32 a0, u32 a1, u32 a2, u32 a3,
                                         u32 b0, u32 b1) {
    asm volatile("mma.sync.aligned.m16n8k16.row.col.f32.bf16.bf16.f32 "
                 "{%0,%1,%2,%3}, {%4,%5,%6,%7}, {%8,%9}, {%0,%1,%2,%3};"
                 : "+f"(c[0]), "+f"(c[1]), "+f"(c[2]), "+f"(c[3])
                 : "r"(a0), "r"(a1), "r"(a2), "r"(a3), "r"(b0), "r"(b1));
}
__device__ __forceinline__ float phi(float x) { return x > 0.0f ? x + 1.0f : __expf(x); }

__device__ __forceinline__ u32 pack_bf16(float a, float b) {
    __nv_bfloat162 h = __floats2bfloat162_rn(a, b);   // low half = a
    return *reinterpret_cast<u32*>(&h);
}
__device__ __forceinline__ void split2(float a, float b, u32& hi, u32& lo) {
    float ha = __bfloat162float(__float2bfloat16(a));
    float hb = __bfloat162float(__float2bfloat16(b));
    hi = pack_bf16(ha, hb);
    lo = pack_bf16(a - ha, b - hb);
}

// ====================================================================
// k1: KV[d][e] = sum_n phi(K[d,n]) * V[e,n]   (TN GEMM, natural layouts)
// grid (SPLIT, BATCH), 256 threads. CTA tile 128x128, warp tile 64x32.
// SMEM tiles: [128 rows][64 tok] bf16, pitch 72 bf16 (144B: 16B-aligned,
// ldmatrix conflict-free since 144/4 = 36 = 4 mod 32).
// ====================================================================
#define P1B 144
#define K1_KHI 0
#define K1_KLO 18432
#define K1_VHI 36864
#define K1_VLO 55296
#define K1_SMEM 73728

__global__ __launch_bounds__(256, 2)
void k1_mma(const float* __restrict__ k, const float* __restrict__ v) {
    extern __shared__ __align__(16) char sm[];
    const u32 sb = smem_u32(sm);
    const int b = blockIdx.y, s = blockIdx.x;
    const int tid = threadIdx.x, wid = tid >> 5, lane = tid & 31;
    const int n4 = tid & 15, dr = tid >> 4;
    const int wd = wid >> 2, we = wid & 3;   // warp tile: d 64, e 32

    const float* kb = k + (size_t)b * DIM * NTOK + (size_t)s * CHUNK;
    const float* vb = v + (size_t)b * DIM * NTOK + (size_t)s * CHUNK;

    float acc[4][4][4];
#pragma unroll
    for (int i = 0; i < 4; i++)
#pragma unroll
        for (int j = 0; j < 4; j++)
#pragma unroll
            for (int r = 0; r < 4; r++) acc[i][j][r] = 0.f;
    float ksum_l[8] = {0.f, 0.f, 0.f, 0.f, 0.f, 0.f, 0.f, 0.f};

    // ldmatrix lane addressing components
    const int rA = (lane & 7) + ((lane & 8) ? 8 : 0);      // A: lanes 8-15 -> row+8
    const int cA = (lane & 16) ? 16 : 0;                   // A: lanes 16+  -> k+8 (16B)
    const int rB = (lane & 7) + ((lane & 16) ? 8 : 0);     // B: lanes 16+  -> row+8
    const int cB = (lane & 8) ? 16 : 0;                    // B: lanes 8-15 -> k+8

    for (int iter = 0; iter < ITERS1; iter++) {
        const int n0 = iter * 64;
        __syncthreads();
        // ---- convert 64-token tiles of phi(K)/V, split hi/lo ----
#pragma unroll
        for (int p = 0; p < 8; p++) {
            const int d = p * 16 + dr;
            const u32 off = (u32)(d * P1B + n4 * 8);
            float4 kx = *(const float4*)(kb + (size_t)d * NTOK + n0 + n4 * 4);
            float f0 = phi(kx.x), f1 = phi(kx.y), f2 = phi(kx.z), f3 = phi(kx.w);
            ksum_l[p] += (f0 + f1) + (f2 + f3);
            uint2 hi, lo;
            split2(f0, f1, hi.x, lo.x);
            split2(f2, f3, hi.y, lo.y);
            *(uint2*)(sm + K1_KHI + off) = hi;
            *(uint2*)(sm + K1_KLO + off) = lo;
            float4 vx = *(const float4*)(vb + (size_t)d * NTOK + n0 + n4 * 4);
            split2(vx.x, vx.y, hi.x, lo.x);
            split2(vx.z, vx.w, hi.y, lo.y);
            *(uint2*)(sm + K1_VHI + off) = hi;
            *(uint2*)(sm + K1_VLO + off) = lo;
        }
        __syncthreads();
        // ---- MMA: 4 k16 steps ----
#pragma unroll
        for (int kk = 0; kk < 4; kk++) {
            u32 bh[8], bl[8];
#pragma unroll
            for (int g = 0; g < 2; g++) {
                const u32 boff = (u32)((we * 32 + g * 16 + rB) * P1B + kk * 32 + cB);
                ldsm4(bh[g*4+0], bh[g*4+1], bh[g*4+2], bh[g*4+3], sb + K1_VHI + boff);
                ldsm4(bl[g*4+0], bl[g*4+1], bl[g*4+2], bl[g*4+3], sb + K1_VLO + boff);
            }
#pragma unroll
            for (int mt = 0; mt < 4; mt++) {
                const u32 aoff = (u32)((wd * 64 + mt * 16 + rA) * P1B + kk * 32 + cA);
                u32 ah0, ah1, ah2, ah3, al0, al1, al2, al3;
                ldsm4(ah0, ah1, ah2, ah3, sb + K1_KHI + aoff);
                ldsm4(al0, al1, al2, al3, sb + K1_KLO + aoff);
#pragma unroll
                for (int nt = 0; nt < 4; nt++) {
                    float* c = acc[mt][nt];
                    const int bi = (nt >> 1) * 4 + (nt & 1) * 2;
                    mma16816(c, ah0, ah1, ah2, ah3, bh[bi], bh[bi+1]);
                    mma16816(c, ah0, ah1, ah2, ah3, bl[bi], bl[bi+1]);
                    mma16816(c, al0, al1, al2, al3, bh[bi], bh[bi+1]);
                }
            }
        }
    }
    __syncthreads();
    // ---- Ksum reduce (reuse smem) ----
    float* kbuf = (float*)sm;
#pragma unroll
    for (int p = 0; p < 8; p++) kbuf[(p * 16 + dr) * 16 + n4] = ksum_l[p];
    __syncthreads();
    if (tid < 128) {
        float sum = 0.f;
#pragma unroll
        for (int i = 0; i < 16; i++) sum += kbuf[tid * 16 + i];
        g_Ksump[b][s][tid] = sum;
    }
    // ---- write fp32 KV partial ----
    float* dst = &g_KVp[b][s][0];
    const int g = lane >> 2, tig = lane & 3;
#pragma unroll
    for (int mt = 0; mt < 4; mt++)
#pragma unroll
        for (int nt = 0; nt < 4; nt++) {
            const int d0 = wd * 64 + mt * 16 + g;
            const int e0 = we * 32 + nt * 8 + tig * 2;
            float* c = acc[mt][nt];
            *(float2*)(dst + d0 * DIM + e0)       = make_float2(c[0], c[1]);
            *(float2*)(dst + (d0 + 8) * DIM + e0) = make_float2(c[2], c[3]);
        }
}

// ====================================================================
// k2: reduce partials -> KV^T bf16 hi/lo + Ksum fp32
// ====================================================================
__global__ __launch_bounds__(256)
void k2_reduce() {
    const int idx = blockIdx.x * 256 + threadIdx.x;
    if (idx < BATCH * DIM * DIM) {
        const int b = idx >> 14, e = idx & 127, d = (idx >> 7) & 127;
        float sum = 0.f;
#pragma unroll
        for (int p = 0; p < SPLIT; p++) sum += g_KVp[b][p][d * DIM + e];
        __nv_bfloat16 h = __float2bfloat16(sum);
        g_KVThi[b][e * DIM + d] = h;
        g_KVTlo[b][e * DIM + d] = __float2bfloat16(sum - __bfloat162float(h));
    }
    if (idx < BATCH * DIM) {
        const int b = idx >> 7, d = idx & 127;
        float sum = 0.f;
#pragma unroll
        for (int p = 0; p < SPLIT; p++) sum += g_Ksump[b][p][d];
        g_Ksum[b][d] = sum;
    }
}

// ====================================================================
// k3: out^T[e][t] = z(t) * sum_d KV^T[e,d] * phi(Q[t,d])
// CTA tile: e=128, t=64 per tile, 16 tiles of the 1024-token chunk.
// Warp tile 64e x 16t (warps 2x4). Pitch 136 bf16 (272B = 16 mod 128: ok).
// ====================================================================
#define P3B 272
#define K3_AHI 0
#define K3_ALO 34816
#define K3_QHI 69632
#define K3_QLO 87040
#define K3_KS  104448   // 128 f32
#define K3_ZS  104960   // 64 f32
#define K3_DEN 105216   // 64*4 f32
#define K3_SMEM 106240

__global__ __launch_bounds__(256, 2)
void k3_mma(const float* __restrict__ q, float* __restrict__ out) {
    extern __shared__ __align__(16) char sm[];
    const u32 sb = smem_u32(sm);
    const int b = blockIdx.y, s = blockIdx.x;
    const int tid = threadIdx.x, wid = tid >> 5, lane = tid & 31;
    const int we = wid >> 2, wt = wid & 3;

    // ---- load KV^T hi/lo into smem once ----
    for (int i = tid; i < DIM * 64; i += 256) {       // u32 units: [e][64 d-pairs]
        const int e = i >> 6, dp = i & 63;
        const u32 off = (u32)(e * P3B + dp * 4);
        *(u32*)(sm + K3_AHI + off) = *(const u32*)(&g_KVThi[b][e * DIM + dp * 2]);
        *(u32*)(sm + K3_ALO + off) = *(const u32*)(&g_KVTlo[b][e * DIM + dp * 2]);
    }
    float* ks   = (float*)(sm + K3_KS);
    float* zs   = (float*)(sm + K3_ZS);
    float* denp = (float*)(sm + K3_DEN);
    if (tid < 128) ks[tid] = g_Ksum[b][tid];
    __syncthreads();

    const float* qb = q + (size_t)b * DIM * NTOK;
    float* ob = out + (size_t)b * DIM * NTOK;

    const int rA = (lane & 7) + ((lane & 8) ? 8 : 0);
    const int cA = (lane & 16) ? 16 : 0;
    const int rB = (lane & 7) + ((lane & 16) ? 8 : 0);
    const int cB = (lane & 8) ? 16 : 0;
    const int g = lane >> 2, tig = lane & 3;

    const int th = wid & 1, dg = wid >> 1;            // conversion roles
    const int tl = th * 32 + lane;

    for (int tile = 0; tile < TILES3; tile++) {
        const int T0 = s * CHUNK + tile * 64;
        __syncthreads();
        // ---- convert/transpose phi(Q) (+ fp32 denominator partials) ----
        float den_l = 0.f;
#pragma unroll
        for (int j = 0; j < 16; j++) {
            const int dp = dg * 16 + j, d0 = dp * 2;
            const float* qp = qb + (size_t)d0 * NTOK + T0 + tl;
            float f0 = phi(qp[0]), f1 = phi(qp[NTOK]);
            u32 hi, lo;
            split2(f0, f1, hi, lo);
            const u32 off = (u32)(tl * P3B + dp * 4);
            *(u32*)(sm + K3_QHI + off) = hi;
            *(u32*)(sm + K3_QLO + off) = lo;
            den_l += f0 * ks[d0] + f1 * ks[d0 + 1];
        }
        denp[tl * 4 + dg] = den_l;
        __syncthreads();
        if (tid < 64) {
            float d4 = denp[tid*4] + denp[tid*4+1] + denp[tid*4+2] + denp[tid*4+3];
            zs[tid] = 1.0f / (d4 + EPS);
        }
        __syncthreads();

        // ---- MMA ----
        float acc[4][2][4];
#pragma unroll
        for (int i = 0; i < 4; i++)
#pragma unroll
            for (int j = 0; j < 2; j++)
#pragma unroll
                for (int r = 0; r < 4; r++) acc[i][j][r] = 0.f;
#pragma unroll
        for (int kk = 0; kk < 8; kk++) {
            const u32 boff = (u32)((wt * 16 + rB) * P3B + kk * 32 + cB);
            u32 bh0, bh1, bh2, bh3, bl0, bl1, bl2, bl3;
            ldsm4(bh0, bh1, bh2, bh3, sb + K3_QHI + boff);
            ldsm4(bl0, bl1, bl2, bl3, sb + K3_QLO + boff);
#pragma unroll
            for (int mt = 0; mt < 4; mt++) {
                const u32 aoff = (u32)((we * 64 + mt * 16 + rA) * P3B + kk * 32 + cA);
                u32 ah0, ah1, ah2, ah3, al0, al1, al2, al3;
                ldsm4(ah0, ah1, ah2, ah3, sb + K3_AHI + aoff);
                ldsm4(al0, al1, al2, al3, sb + K3_ALO + aoff);
                mma16816(acc[mt][0], ah0, ah1, ah2, ah3, bh0, bh1);
                mma16816(acc[mt][0], ah0, ah1, ah2, ah3, bl0, bl1);
                mma16816(acc[mt][0], al0, al1, al2, al3, bh0, bh1);
                mma16816(acc[mt][1], ah0, ah1, ah2, ah3, bh2, bh3);
                mma16816(acc[mt][1], ah0, ah1, ah2, ah3, bl2, bl3);
                mma16816(acc[mt][1], al0, al1, al2, al3, bh2, bh3);
            }
        }
        // ---- epilogue: scale by z, store out^T ----
#pragma unroll
        for (int mt = 0; mt < 4; mt++)
#pragma unroll
            for (int nt = 0; nt < 2; nt++) {
                const int e0 = we * 64 + mt * 16 + g;
                const int lt = wt * 16 + nt * 8 + tig * 2;
                const float z0 = zs[lt], z1 = zs[lt + 1];
                float* c = acc[mt][nt];
                *(float2*)(ob + (size_t)e0 * NTOK + T0 + lt) =
                    make_float2(c[0] * z0, c[1] * z1);
                *(float2*)(ob + (size_t)(e0 + 8) * NTOK + T0 + lt) =
                    make_float2(c[2] * z0, c[3] * z1);
            }
    }
}

// ====================================================================
extern "C" void kernel_launch(void* const* d_in, const int* in_sizes, int n_in,
                              void* d_out, int out_size) {
    const float* q = (const float*)d_in[0];
    const float* k = (const float*)d_in[1];
    const float* v = (const float*)d_in[2];
    float* out = (float*)d_out;

    cudaFuncSetAttribute(k1_mma, cudaFuncAttributeMaxDynamicSharedMemorySize, K1_SMEM);
    cudaFuncSetAttribute(k3_mma, cudaFuncAttributeMaxDynamicSharedMemorySize, K3_SMEM);

    k1_mma<<<dim3(SPLIT, BATCH), 256, K1_SMEM>>>(k, v);
    k2_reduce<<<(BATCH * DIM * DIM + 255) / 256, 256>>>();
    k3_mma<<<dim3(SPLIT, BATCH), 256, K3_SMEM>>>(q, out);
}